// round 3
// baseline (speedup 1.0000x reference)
#include <cuda_runtime.h>
#include <cstdint>

#define BQ    64
#define DIMS  256
#define RDEG  32
#define EF    32
#define KOUT  10
#define NPTS  100000
#define VIS_WORDS ((NPTS + 31) / 32)   // 3125

__device__ __forceinline__ unsigned long long shfl_xor64(unsigned long long v, int m) {
    return __shfl_xor_sync(0xffffffffu, v, m);
}
__device__ __forceinline__ unsigned long long u64min(unsigned long long a, unsigned long long b) {
    return a < b ? a : b;
}
__device__ __forceinline__ unsigned long long u64max(unsigned long long a, unsigned long long b) {
    return a > b ? a : b;
}

// Warp-collective squared distance: storage row `id` vs query in qs (as float4[64]).
// Perfect binary-tree fp32 summation (in-lane pairwise + shfl-xor tree) for
// minimal deviation from XLA's tree reduce.
__device__ __forceinline__ float warp_sqdist(const float* __restrict__ storage,
                                             int id, const float4* qs, int lane) {
    const float4* row = (const float4*)(storage + (size_t)id * DIMS);
    float4 a0 = row[lane], a1 = row[lane + 32];
    float4 b0 = qs[lane],  b1 = qs[lane + 32];
    float d0 = a0.x - b0.x, d1 = a0.y - b0.y, d2 = a0.z - b0.z, d3 = a0.w - b0.w;
    float e0 = a1.x - b1.x, e1 = a1.y - b1.y, e2 = a1.z - b1.z, e3 = a1.w - b1.w;
    float s = ((d0 * d0 + d1 * d1) + (d2 * d2 + d3 * d3))
            + ((e0 * e0 + e1 * e1) + (e2 * e2 + e3 * e3));
#pragma unroll
    for (int o = 16; o; o >>= 1) s += __shfl_xor_sync(0xffffffffu, s, o);
    return s;
}

__global__ __launch_bounds__(1024, 1)
void nsw_search_kernel(const float* __restrict__ query,
                       const float* __restrict__ storage,
                       const int*   __restrict__ graph,
                       const int*   __restrict__ initial,
                       float*       __restrict__ out) {
    __shared__ unsigned int vis[VIS_WORDS];   // visited bitset, 12.5 KB
    __shared__ float4       qs[64];           // query vector (256 floats)
    __shared__ int          cid[EF];          // candidate ids
    __shared__ unsigned int cdb[EF];          // candidate dist bits (fp32, non-negative)
    __shared__ unsigned int expf[EF];         // per-slot expanded flag
    __shared__ int          nbid[RDEG];       // neighbor ids of the expanded node
    __shared__ unsigned int freshm[RDEG];     // neighbor freshness
    __shared__ unsigned int ndb[RDEG];        // neighbor dist bits

    const int b    = blockIdx.x;
    const int tid  = threadIdx.x;
    const int w    = tid >> 5;
    const int lane = tid & 31;
    const unsigned int INFB = __float_as_uint(1e30f);

    // ---- init ----
    for (int i = tid; i < VIS_WORDS; i += 1024) vis[i] = 0u;
    if (tid < 64) qs[tid] = ((const float4*)(query + (size_t)b * DIMS))[tid];
    if (w == 0) {
        cid[lane]  = initial[b * EF + lane];
        expf[lane] = 0u;
    }
    __syncthreads();

    if (w == 0) {
        int id = cid[lane];
        atomicOr(&vis[id >> 5], 1u << (id & 31));  // visited[init] = True
    }
    // initial candidate distances: warp w handles cid[w]
    {
        float s = warp_sqdist(storage, cid[w], qs, lane);
        if (lane == 0) cdb[w] = __float_as_uint(s);
    }
    __syncthreads();

    // ---- ef_search greedy expansion steps ----
    for (int step = 0; step < EF; ++step) {
        // Phase 1 (warp 0): pick closest unexpanded, mark expanded, fetch graph
        // row, read freshness for ALL neighbors, then mark visited.
        if (w == 0) {
            unsigned int pd = expf[lane] ? INFB : cdb[lane];
            unsigned long long key = ((unsigned long long)pd << 32) | (unsigned)lane;
#pragma unroll
            for (int o = 16; o; o >>= 1) key = u64min(key, shfl_xor64(key, o));
            int j = (int)(key & 63u);
            int u = cid[j];                       // jnp.argmin: first-min tie-break
            if (cid[lane] == u) expf[lane] = 1u;  // expanded.at[u].set(True) semantics

            int nb = graph[(size_t)u * RDEG + lane];
            unsigned int word  = vis[nb >> 5];
            unsigned int fresh = ((word >> (nb & 31)) & 1u) ^ 1u;
            nbid[lane]   = nb;
            freshm[lane] = fresh;
            __syncwarp();                          // all freshness reads before any write
            atomicOr(&vis[nb >> 5], 1u << (nb & 31));
        }
        __syncthreads();

        // Phase 2 (all 32 warps): warp w computes distance to neighbor w.
        {
            unsigned int res = INFB;
            if (freshm[w]) {                      // uniform within warp
                float s = warp_sqdist(storage, nbid[w], qs, lane);
                res = __float_as_uint(s);
            }
            if (lane == 0) ndb[w] = res;
        }
        __syncthreads();

        // Phase 3 (warp 0): stable 64-element sort == lax.top_k(-all_d, EF).
        // key = dist_bits(32) | slot(6 @bit25) | id(17 @bit1) | exp(bit0).
        // (dist, slot) is unique => exact stable ascending order by (dist, index).
        if (w == 0) {
            unsigned long long ka =
                ((unsigned long long)cdb[lane] << 32) |
                ((unsigned long long)(unsigned)lane << 25) |
                ((unsigned long long)(unsigned)cid[lane] << 1) |
                (unsigned long long)expf[lane];
            unsigned long long kb =
                ((unsigned long long)ndb[lane] << 32) |
                ((unsigned long long)(unsigned)(lane + 32) << 25) |
                ((unsigned long long)(unsigned)nbid[lane] << 1);   // exp = 0

            // Bitonic sort of 64 elements: element lane in ka, lane+32 in kb.
#pragma unroll
            for (int k = 2; k <= 32; k <<= 1) {
#pragma unroll
                for (int j = k >> 1; j >= 1; j >>= 1) {
                    {   // reg a: e = lane
                        bool up    = ((lane & k) == 0);
                        bool lower = ((lane & j) == 0);
                        unsigned long long o = shfl_xor64(ka, j);
                        ka = (up == lower) ? u64min(ka, o) : u64max(ka, o);
                    }
                    {   // reg b: e = lane + 32
                        int  e     = lane + 32;
                        bool up    = ((e & k) == 0);
                        bool lower = ((e & j) == 0);
                        unsigned long long o = shfl_xor64(kb, j);
                        kb = (up == lower) ? u64min(kb, o) : u64max(kb, o);
                    }
                }
            }
            // Final merge k = 64 (all ascending). j = 32 is the in-lane exchange.
            {
                unsigned long long lo = u64min(ka, kb), hi = u64max(ka, kb);
                ka = lo; kb = hi;
            }
#pragma unroll
            for (int j = 16; j >= 1; j >>= 1) {
                {
                    bool lower = ((lane & j) == 0);
                    unsigned long long o = shfl_xor64(ka, j);
                    ka = lower ? u64min(ka, o) : u64max(ka, o);
                }
                {
                    bool lower = ((lane & j) == 0);
                    unsigned long long o = shfl_xor64(kb, j);
                    kb = lower ? u64min(kb, o) : u64max(kb, o);
                }
            }
            // keep best EF=32 (elements 0..31 live in ka across the warp)
            cdb[lane]  = (unsigned int)(ka >> 32);
            cid[lane]  = (int)((ka >> 1) & 0x1FFFFu);
            expf[lane] = (unsigned int)(ka & 1u);
        }
        __syncthreads();
    }

    // ---- output: final top_k(-cd, 10) == first 10 of the sorted pool ----
    // Tuple outputs flattened+concatenated: ids[B*K] then dists[B*K], as float32.
    if (w == 0 && lane < KOUT) {
        out[b * KOUT + lane]             = (float)cid[lane];
        out[BQ * KOUT + b * KOUT + lane] = __uint_as_float(cdb[lane]);
    }
}

extern "C" void kernel_launch(void* const* d_in, const int* in_sizes, int n_in,
                              void* d_out, int out_size) {
    const float* query   = (const float*)d_in[0];
    const float* storage = (const float*)d_in[1];
    const int*   graph   = (const int*)d_in[2];
    const int*   initial = (const int*)d_in[3];
    (void)in_sizes; (void)n_in; (void)out_size;
    nsw_search_kernel<<<BQ, 1024>>>(query, storage, graph, initial, (float*)d_out);
}

// round 4
// speedup vs baseline: 1.0045x; 1.0045x over previous
#include <cuda_runtime.h>
#include <cstdint>

#define BQ    64
#define DIMS  256
#define RDEG  32
#define EF    32
#define KOUT  10
#define NPTS  100000
#define VIS_WORDS ((NPTS + 31) / 32)   // 3125

__device__ __forceinline__ unsigned long long shfl_xor64(unsigned long long v, int m) {
    return __shfl_xor_sync(0xffffffffu, v, m);
}
__device__ __forceinline__ unsigned long long u64min(unsigned long long a, unsigned long long b) {
    return a < b ? a : b;
}
__device__ __forceinline__ unsigned long long u64max(unsigned long long a, unsigned long long b) {
    return a > b ? a : b;
}

// Warp-collective squared distance: storage row `id` vs query in qs (as float4[64]).
// Perfect binary-tree fp32 summation (in-lane pairwise + shfl-xor tree) for
// minimal deviation from XLA's tree reduce.
__device__ __forceinline__ float warp_sqdist(const float* __restrict__ storage,
                                             int id, const float4* qs, int lane) {
    const float4* row = (const float4*)(storage + (size_t)id * DIMS);
    float4 a0 = row[lane], a1 = row[lane + 32];
    float4 b0 = qs[lane],  b1 = qs[lane + 32];
    float d0 = a0.x - b0.x, d1 = a0.y - b0.y, d2 = a0.z - b0.z, d3 = a0.w - b0.w;
    float e0 = a1.x - b1.x, e1 = a1.y - b1.y, e2 = a1.z - b1.z, e3 = a1.w - b1.w;
    float s = ((d0 * d0 + d1 * d1) + (d2 * d2 + d3 * d3))
            + ((e0 * e0 + e1 * e1) + (e2 * e2 + e3 * e3));
#pragma unroll
    for (int o = 16; o; o >>= 1) s += __shfl_xor_sync(0xffffffffu, s, o);
    return s;
}

__global__ __launch_bounds__(1024, 1)
void nsw_search_kernel(const float* __restrict__ query,
                       const float* __restrict__ storage,
                       const int*   __restrict__ graph,
                       const int*   __restrict__ initial,
                       float*       __restrict__ out) {
    __shared__ unsigned int vis[VIS_WORDS];   // visited bitset, 12.5 KB
    __shared__ float4       qs[64];           // query vector (256 floats)
    __shared__ int          cid[EF];          // candidate ids
    __shared__ unsigned int cdb[EF];          // candidate dist bits (fp32, non-negative)
    __shared__ unsigned int expf[EF];         // per-slot expanded flag
    __shared__ int          nbid[RDEG];       // neighbor ids of the expanded node
    __shared__ unsigned int freshm[RDEG];     // neighbor freshness
    __shared__ unsigned int ndb[RDEG];        // neighbor dist bits

    const int b    = blockIdx.x;
    const int tid  = threadIdx.x;
    const int w    = tid >> 5;
    const int lane = tid & 31;
    const unsigned int INFB = __float_as_uint(1e30f);

    // ---- init ----
    for (int i = tid; i < VIS_WORDS; i += 1024) vis[i] = 0u;
    if (tid < 64) qs[tid] = ((const float4*)(query + (size_t)b * DIMS))[tid];
    if (w == 0) {
        cid[lane]  = initial[b * EF + lane];
        expf[lane] = 0u;
    }
    __syncthreads();

    if (w == 0) {
        int id = cid[lane];
        atomicOr(&vis[id >> 5], 1u << (id & 31));  // visited[init] = True
    }
    // initial candidate distances: warp w handles cid[w]
    {
        float s = warp_sqdist(storage, cid[w], qs, lane);
        if (lane == 0) cdb[w] = __float_as_uint(s);
    }
    __syncthreads();

    // ---- ef_search greedy expansion steps ----
    for (int step = 0; step < EF; ++step) {
        // Phase 1 (warp 0): pick closest unexpanded, mark expanded, fetch graph
        // row, read freshness for ALL neighbors, then mark visited.
        if (w == 0) {
            unsigned int pd = expf[lane] ? INFB : cdb[lane];
            unsigned long long key = ((unsigned long long)pd << 32) | (unsigned)lane;
#pragma unroll
            for (int o = 16; o; o >>= 1) key = u64min(key, shfl_xor64(key, o));
            int j = (int)(key & 63u);
            int u = cid[j];                       // jnp.argmin: first-min tie-break
            if (cid[lane] == u) expf[lane] = 1u;  // expanded.at[u].set(True) semantics

            int nb = graph[(size_t)u * RDEG + lane];
            unsigned int word  = vis[nb >> 5];
            unsigned int fresh = ((word >> (nb & 31)) & 1u) ^ 1u;
            nbid[lane]   = nb;
            freshm[lane] = fresh;
            __syncwarp();                          // all freshness reads before any write
            atomicOr(&vis[nb >> 5], 1u << (nb & 31));
        }
        __syncthreads();

        // Phase 2 (all 32 warps): warp w computes distance to neighbor w.
        {
            unsigned int res = INFB;
            if (freshm[w]) {                      // uniform within warp
                float s = warp_sqdist(storage, nbid[w], qs, lane);
                res = __float_as_uint(s);
            }
            if (lane == 0) ndb[w] = res;
        }
        __syncthreads();

        // Phase 3 (warp 0): stable 64-element sort == lax.top_k(-all_d, EF).
        // key = dist_bits(32) | slot(6 @bit25) | id(17 @bit1) | exp(bit0).
        // (dist, slot) is unique => exact stable ascending order by (dist, index).
        if (w == 0) {
            unsigned long long ka =
                ((unsigned long long)cdb[lane] << 32) |
                ((unsigned long long)(unsigned)lane << 25) |
                ((unsigned long long)(unsigned)cid[lane] << 1) |
                (unsigned long long)expf[lane];
            unsigned long long kb =
                ((unsigned long long)ndb[lane] << 32) |
                ((unsigned long long)(unsigned)(lane + 32) << 25) |
                ((unsigned long long)(unsigned)nbid[lane] << 1);   // exp = 0

            // Bitonic sort of 64 elements: element lane in ka, lane+32 in kb.
#pragma unroll
            for (int k = 2; k <= 32; k <<= 1) {
#pragma unroll
                for (int j = k >> 1; j >= 1; j >>= 1) {
                    {   // reg a: e = lane
                        bool up    = ((lane & k) == 0);
                        bool lower = ((lane & j) == 0);
                        unsigned long long o = shfl_xor64(ka, j);
                        ka = (up == lower) ? u64min(ka, o) : u64max(ka, o);
                    }
                    {   // reg b: e = lane + 32
                        int  e     = lane + 32;
                        bool up    = ((e & k) == 0);
                        bool lower = ((e & j) == 0);
                        unsigned long long o = shfl_xor64(kb, j);
                        kb = (up == lower) ? u64min(kb, o) : u64max(kb, o);
                    }
                }
            }
            // Final merge k = 64 (all ascending). j = 32 is the in-lane exchange.
            {
                unsigned long long lo = u64min(ka, kb), hi = u64max(ka, kb);
                ka = lo; kb = hi;
            }
#pragma unroll
            for (int j = 16; j >= 1; j >>= 1) {
                {
                    bool lower = ((lane & j) == 0);
                    unsigned long long o = shfl_xor64(ka, j);
                    ka = lower ? u64min(ka, o) : u64max(ka, o);
                }
                {
                    bool lower = ((lane & j) == 0);
                    unsigned long long o = shfl_xor64(kb, j);
                    kb = lower ? u64min(kb, o) : u64max(kb, o);
                }
            }
            // keep best EF=32 (elements 0..31 live in ka across the warp)
            cdb[lane]  = (unsigned int)(ka >> 32);
            cid[lane]  = (int)((ka >> 1) & 0x1FFFFu);
            expf[lane] = (unsigned int)(ka & 1u);
        }
        __syncthreads();
    }

    // ---- output: final top_k(-cd, 10) == first 10 of the sorted pool ----
    // Tuple outputs flattened+concatenated: ids[B*K] then dists[B*K], as float32.
    if (w == 0 && lane < KOUT) {
        out[b * KOUT + lane]             = (float)cid[lane];
        out[BQ * KOUT + b * KOUT + lane] = __uint_as_float(cdb[lane]);
    }
}

extern "C" void kernel_launch(void* const* d_in, const int* in_sizes, int n_in,
                              void* d_out, int out_size) {
    const float* query   = (const float*)d_in[0];
    const float* storage = (const float*)d_in[1];
    const int*   graph   = (const int*)d_in[2];
    const int*   initial = (const int*)d_in[3];
    (void)in_sizes; (void)n_in; (void)out_size;
    nsw_search_kernel<<<BQ, 1024>>>(query, storage, graph, initial, (float*)d_out);
}

// round 5
// speedup vs baseline: 1.3513x; 1.3452x over previous
#include <cuda_runtime.h>
#include <cstdint>

#define BQ    64
#define DIMS  256
#define RDEG  32
#define EF    32
#define KOUT  10
#define NPTS  100000
#define VIS_WORDS ((NPTS + 31) / 32)   // 3125

typedef unsigned long long u64;

__device__ __forceinline__ u64 shfl_xor64(u64 v, int m) {
    return __shfl_xor_sync(0xffffffffu, v, m);
}
__device__ __forceinline__ u64 u64min(u64 a, u64 b) { return a < b ? a : b; }
__device__ __forceinline__ u64 u64max(u64 a, u64 b) { return a > b ? a : b; }

// One compare-exchange stage of a bitonic network on a per-lane u64 key.
#define BSTAGE(v, kk, jj) {                                        \
    u64 _o = shfl_xor64(v, jj);                                    \
    bool _up    = ((lane & (kk)) == 0);                            \
    bool _lower = ((lane & (jj)) == 0);                            \
    v = (_up == _lower) ? u64min(v, _o) : u64max(v, _o); }

// Full ascending bitonic sort of 32 u64 keys (one per lane), 15 stages.
#define SORT32(v) {                                                \
    BSTAGE(v, 2, 1);                                               \
    BSTAGE(v, 4, 2);  BSTAGE(v, 4, 1);                             \
    BSTAGE(v, 8, 4);  BSTAGE(v, 8, 2);  BSTAGE(v, 8, 1);           \
    BSTAGE(v, 16, 8); BSTAGE(v, 16, 4); BSTAGE(v, 16, 2); BSTAGE(v, 16, 1); \
    BSTAGE(v, 32, 16);BSTAGE(v, 32, 8); BSTAGE(v, 32, 4); BSTAGE(v, 32, 2); BSTAGE(v, 32, 1); }

// Warp-collective squared distance: storage row `id` vs query held in regs.
// Perfect binary-tree fp32 summation (in-lane pairwise + shfl-xor tree).
__device__ __forceinline__ float warp_sqdist(const float* __restrict__ storage,
                                             int id, float4 b0, float4 b1, int lane) {
    const float4* row = (const float4*)(storage + (size_t)id * DIMS);
    float4 a0 = row[lane], a1 = row[lane + 32];
    float d0 = a0.x - b0.x, d1 = a0.y - b0.y, d2 = a0.z - b0.z, d3 = a0.w - b0.w;
    float e0 = a1.x - b1.x, e1 = a1.y - b1.y, e2 = a1.z - b1.z, e3 = a1.w - b1.w;
    float s = ((d0 * d0 + d1 * d1) + (d2 * d2 + d3 * d3))
            + ((e0 * e0 + e1 * e1) + (e2 * e2 + e3 * e3));
#pragma unroll
    for (int o = 16; o; o >>= 1) s += __shfl_xor_sync(0xffffffffu, s, o);
    return s;
}

__global__ __launch_bounds__(1024, 1)
void nsw_search_kernel(const float* __restrict__ query,
                       const float* __restrict__ storage,
                       const int*   __restrict__ graph,
                       const int*   __restrict__ initial,
                       float*       __restrict__ out) {
    __shared__ unsigned int vis[VIS_WORDS];   // visited bitset, 12.5 KB
    __shared__ int          nbid[RDEG];       // neighbor ids of expanded node
    __shared__ unsigned int freshm[RDEG];     // neighbor freshness
    __shared__ unsigned int ndb[RDEG];        // neighbor dist bits
    __shared__ int          initids[EF];
    __shared__ unsigned int initdb[EF];

    const int b    = blockIdx.x;
    const int tid  = threadIdx.x;
    const int w    = tid >> 5;
    const int lane = tid & 31;
    const unsigned int INFB = __float_as_uint(1e30f);

    // Query vector lives in registers (same lanes every distance eval).
    const float4* qrow = (const float4*)(query + (size_t)b * DIMS);
    const float4 q0 = qrow[lane], q1 = qrow[lane + 32];

    // ---- init ----
    for (int i = tid; i < VIS_WORDS; i += 1024) vis[i] = 0u;
    if (w == 0) initids[lane] = __ldg(initial + b * EF + lane);
    __syncthreads();

    // initial candidate distances (warp w -> initids[w]); warp 1 marks visited
    {
        float s = warp_sqdist(storage, initids[w], q0, q1, lane);
        if (lane == 0) initdb[w] = __float_as_uint(s);
    }
    if (w == 1) {
        int id = initids[lane];
        atomicOr(&vis[id >> 5], 1u << (id & 31));        // visited[init] = True
    }
    __syncthreads();

    u64 ka = 0;   // sorted candidate pool key: dist(32)|slot(6)@25|id(17)@1|exp(1)@0
    if (w == 0) {
        // keys from the (unsorted) initial pool; slot = original index (stability)
        ka = ((u64)initdb[lane] << 32) | ((u64)(unsigned)lane << 25)
           | ((u64)(unsigned)initids[lane] << 1);
        // pick u0 = argmin (all unexpanded); issue its graph row load immediately
        u64 mk = ka;
#pragma unroll
        for (int o = 16; o; o >>= 1) mk = u64min(mk, shfl_xor64(mk, o));
        const int u = (int)((mk >> 1) & 0x1FFFFu);
        const int nb = __ldg(graph + (size_t)u * RDEG + lane);   // overlaps the sort
        // sort pool (top_k-stable order == (d, orig slot))
        SORT32(ka);
        // rebuild: slot = sorted rank; mark exp for id == u
        {
            unsigned int d = (unsigned int)(ka >> 32);
            int id = (int)((ka >> 1) & 0x1FFFFu);
            unsigned int e = (id == u) ? 1u : 0u;
            ka = ((u64)d << 32) | ((u64)(unsigned)lane << 25) | ((u64)(unsigned)id << 1) | e;
        }
        // prefetch neighbor storage rows into L2 (8 x 128B lines per row)
        {
            const float* rp = storage + (size_t)nb * DIMS;
#pragma unroll
            for (int i = 0; i < 8; i++)
                asm volatile("prefetch.global.L2 [%0];" :: "l"(rp + i * 32));
        }
        // freshness: read for ALL neighbors before any visited write
        unsigned int word  = vis[nb >> 5];
        unsigned int fresh = ((word >> (nb & 31)) & 1u) ^ 1u;
        nbid[lane]   = nb;
        freshm[lane] = fresh;
        __syncwarp();
        atomicOr(&vis[nb >> 5], 1u << (nb & 31));
    }
    __syncthreads();

    // ---- ef_search expansion steps; pool stays sorted (invariant == top_k order)
    for (int t = 0; t < EF; ++t) {
        // Phase 2 (all 32 warps): warp w computes distance to neighbor w.
        {
            unsigned int res = INFB;
            if (freshm[w]) {
                float s = warp_sqdist(storage, nbid[w], q0, q1, lane);
                res = __float_as_uint(s);
            }
            if (lane == 0) ndb[w] = res;
        }
        __syncthreads();

        // Phase 3 (warp 0): pick next u BEFORE the merge (the min-key unexpanded
        // entry always survives into the top-32), issue its graph load, then
        // sort neighbors + merge while the load is in flight.
        if (w == 0) {
            u64 kb = ((u64)ndb[lane] << 32) | ((u64)(unsigned)(lane + 32) << 25)
                   | ((u64)(unsigned)nbid[lane] << 1);           // exp = 0

            const bool more = (t < EF - 1);
            int u = 0, nb = 0;
            if (more) {
                u64 mk = u64min((ka & 1ull) ? ~0ull : ka, kb);   // mask expanded pool entries
#pragma unroll
                for (int o = 16; o; o >>= 1) mk = u64min(mk, shfl_xor64(mk, o));
                u  = (int)((mk >> 1) & 0x1FFFFu);
                nb = __ldg(graph + (size_t)u * RDEG + lane);     // overlaps the sort
            }

            // sort the 32 neighbor keys (pool ka is already sorted)
            SORT32(kb);
            // top-32 of two ascending 32-seqs: min against reversed, then 5-stage merge
            u64 lo = u64min(ka, shfl_xor64(kb, 31));
#pragma unroll
            for (int j = 16; j >= 1; j >>= 1) {
                u64 o = shfl_xor64(lo, j);
                lo = ((lane & j) == 0) ? u64min(lo, o) : u64max(lo, o);
            }
            // rebuild sorted pool: slot = rank; mark exp for id == u_next
            {
                unsigned int d = (unsigned int)(lo >> 32);
                int id = (int)((lo >> 1) & 0x1FFFFu);
                unsigned int e = (unsigned int)(lo & 1ull);
                if (more && id == u) e = 1u;
                ka = ((u64)d << 32) | ((u64)(unsigned)lane << 25) | ((u64)(unsigned)id << 1) | e;
            }

            if (more) {
                // prefetch next step's storage rows while finishing bookkeeping
                const float* rp = storage + (size_t)nb * DIMS;
#pragma unroll
                for (int i = 0; i < 8; i++)
                    asm volatile("prefetch.global.L2 [%0];" :: "l"(rp + i * 32));
                // freshness reads before any visited write
                unsigned int word  = vis[nb >> 5];
                unsigned int fresh = ((word >> (nb & 31)) & 1u) ^ 1u;
                nbid[lane]   = nb;
                freshm[lane] = fresh;
                __syncwarp();
                atomicOr(&vis[nb >> 5], 1u << (nb & 31));
            }
        }
        __syncthreads();
    }

    // ---- output: final top_k(-cd, 10) == first 10 of the sorted pool ----
    // Tuple outputs flattened+concatenated: ids[B*K] then dists[B*K], as float32.
    if (w == 0 && lane < KOUT) {
        out[b * KOUT + lane]             = (float)((ka >> 1) & 0x1FFFFu);
        out[BQ * KOUT + b * KOUT + lane] = __uint_as_float((unsigned int)(ka >> 32));
    }
}

extern "C" void kernel_launch(void* const* d_in, const int* in_sizes, int n_in,
                              void* d_out, int out_size) {
    const float* query   = (const float*)d_in[0];
    const float* storage = (const float*)d_in[1];
    const int*   graph   = (const int*)d_in[2];
    const int*   initial = (const int*)d_in[3];
    (void)in_sizes; (void)n_in; (void)out_size;
    nsw_search_kernel<<<BQ, 1024>>>(query, storage, graph, initial, (float*)d_out);
}